// round 2
// baseline (speedup 1.0000x reference)
#include <cuda_runtime.h>
#include <cstddef>

#define MM 1536
#define STRIPS 48
#define TSTEPS 1568   /* multiple of 8, >= MM + 31 */

// Boundary rows between strips (SoA so the consumer can batch-load), plus
// progress flags. Rewritten every launch; flags re-zeroed by init kernel.
__device__ float g_bM[STRIPS][MM + 24];
__device__ float g_bX[STRIPS][MM + 24];
__device__ float g_bY[STRIPS][MM + 24];
__device__ int   g_prog[STRIPS];

__global__ void hmm_init_kernel() {
    if (threadIdx.x < STRIPS) g_prog[threadIdx.x] = 0;
}

__device__ __forceinline__ float ex2_(float x) {
    float y; asm("ex2.approx.ftz.f32 %0, %1;" : "=f"(y) : "f"(x)); return y;
}
__device__ __forceinline__ float lg2_(float x) {
    float y; asm("lg2.approx.ftz.f32 %0, %1;" : "=f"(y) : "f"(x)); return y;
}

// logsumexp of 3 in base-2 domain; only 2 ex2 (the max term is exactly 1).
__device__ __forceinline__ float lse3_(float a, float b, float c) {
    float hi = fmaxf(a, b), lo = fminf(a, b);
    float m  = fmaxf(hi, c), s2 = fminf(hi, c);
    return m + lg2_(1.0f + ex2_(lo - m) + ex2_(s2 - m));
}

#define L2E  1.4426950408889634f
#define LN2  0.6931471805599453f
#define NEGB (-1.0e8f * L2E)

__global__ void __launch_bounds__(32, 1)
hmm_fwd_kernel(const float* __restrict__ theta, float* __restrict__ out)
{
    const int g = blockIdx.x;    // strip: rows 32g+1 .. 32g+32 (DP indexing)
    const int r = threadIdx.x;   // lane -> DP row 32g + r + 1
    const float* tb = theta + (size_t)(g * 32 + r) * (MM * 9);

    // v* : V(row, j) of the lane's most recently computed cell (log2 domain)
    float vM = NEGB, vX = NEGB, vY = NEGB;
    // du* : "diag" = the up-value used one step earlier
    float duM, duX, duY;
    duM = duX = duY = (g == 0 && r == 0) ? 0.0f : NEGB;  // V(0,0)=0 for top strip

    // Boundary window (lane 0, g>0): bq[q] = boundary col (t0+1+q)
    float bqM[8], bqX[8], bqY[8];
    float tmpM[4], tmpX[4], tmpY[4];
    #pragma unroll
    for (int q = 0; q < 8; q++) { bqM[q] = NEGB; bqX[q] = NEGB; bqY[q] = NEGB; }
    #pragma unroll
    for (int q = 0; q < 4; q++) { tmpM[q] = NEGB; tmpX[q] = NEGB; tmpY[q] = NEGB; }
    int avail = 0;

    // Theta double-buffer: 4 steps per group, 9 potentials per step (pre-scaled by log2 e)
    float thA[4][9], thB[4][9];

    auto loadGroup = [&](int tbase, float (&dst)[4][9]) {
        #pragma unroll
        for (int q = 0; q < 4; q++) {
            int col = tbase + q - r;
            int cc  = col < 0 ? 0 : (col >= MM ? MM - 1 : col);  // clamp; inactive lanes discard
            const float* p = tb + (size_t)cc * 9;
            #pragma unroll
            for (int e = 0; e < 9; e++) dst[q][e] = __ldg(p + e) * L2E;
        }
    };

    auto pollLoad = [&](int t0) {  // prefetch boundary cols t0+9..t0+12
        if (g > 0 && r == 0) {
            int need = t0 + 12; if (need > MM) need = MM;
            if (avail < need) {
                do { avail = *((volatile int*)&g_prog[g - 1]); } while (avail < need);
                __threadfence();
            }
            #pragma unroll
            for (int q = 0; q < 4; q++) {
                int c = t0 + 9 + q; if (c > MM) c = MM;
                tmpM[q] = g_bM[g - 1][c];
                tmpX[q] = g_bX[g - 1][c];
                tmpY[q] = g_bY[g - 1][c];
            }
        }
    };
    auto shiftB = [&]() {
        if (g > 0 && r == 0) {
            #pragma unroll
            for (int q = 0; q < 4; q++) {
                bqM[q] = bqM[q + 4]; bqX[q] = bqX[q + 4]; bqY[q] = bqY[q + 4];
                bqM[q + 4] = tmpM[q]; bqX[q + 4] = tmpX[q]; bqY[q + 4] = tmpY[q];
            }
        }
    };

    auto step = [&](int t, const float (&th)[9], float bM_, float bX_, float bY_) {
        // up = neighbor lane's value from the previous step
        float nuM = __shfl_up_sync(0xffffffffu, vM, 1);
        float nuX = __shfl_up_sync(0xffffffffu, vX, 1);
        float nuY = __shfl_up_sync(0xffffffffu, vY, 1);
        if (r == 0) { nuM = bM_; nuX = bX_; nuY = bY_; }
        int col = t - r;                     // theta column (0-based); DP col = col+1
        if ((unsigned)col < (unsigned)MM) {
            float a = lse3_(duM + th[0], duX + th[1], duY + th[2]);  // Match  <- diag
            float b = lse3_(nuM + th[3], nuX + th[4], nuY + th[5]);  // X      <- up
            float c = lse3_(vM  + th[6], vX  + th[7], vY  + th[8]);  // Y      <- left
            vM = a; vX = b; vY = c;
            if (r == 31 && g < STRIPS - 1) {
                int j = col + 1;
                g_bM[g][j] = a; g_bX[g][j] = b; g_bY[g][j] = c;
                if ((j & 7) == 0 || j == MM) {
                    __threadfence();
                    *((volatile int*)&g_prog[g]) = j;
                }
            }
        }
        duM = nuM; duX = nuX; duY = nuY;     // this step's up = next step's diag
    };

    // ---- prologue ----
    loadGroup(0, thA);
    if (g > 0 && r == 0) {
        do { avail = *((volatile int*)&g_prog[g - 1]); } while (avail < 8);
        __threadfence();
        #pragma unroll
        for (int q = 0; q < 8; q++) {
            bqM[q] = g_bM[g - 1][1 + q];
            bqX[q] = g_bX[g - 1][1 + q];
            bqY[q] = g_bY[g - 1][1 + q];
        }
    }

    const bool z = (g == 0);  // top strip: row above is the V[0,:] border (= NEGB for col >= 1)

    // ---- main loop: 2 groups of 4 steps per iteration (theta ping-pong) ----
    for (int t0 = 0; t0 < TSTEPS; t0 += 8) {
        pollLoad(t0);
        loadGroup(t0 + 4, thB);
        step(t0 + 0, thA[0], z ? NEGB : bqM[0], z ? NEGB : bqX[0], z ? NEGB : bqY[0]);
        step(t0 + 1, thA[1], z ? NEGB : bqM[1], z ? NEGB : bqX[1], z ? NEGB : bqY[1]);
        step(t0 + 2, thA[2], z ? NEGB : bqM[2], z ? NEGB : bqX[2], z ? NEGB : bqY[2]);
        step(t0 + 3, thA[3], z ? NEGB : bqM[3], z ? NEGB : bqX[3], z ? NEGB : bqY[3]);
        shiftB();

        pollLoad(t0 + 4);
        loadGroup(t0 + 8, thA);
        step(t0 + 4, thB[0], z ? NEGB : bqM[0], z ? NEGB : bqX[0], z ? NEGB : bqY[0]);
        step(t0 + 5, thB[1], z ? NEGB : bqM[1], z ? NEGB : bqX[1], z ? NEGB : bqY[1]);
        step(t0 + 6, thB[2], z ? NEGB : bqM[2], z ? NEGB : bqX[2], z ? NEGB : bqY[2]);
        step(t0 + 7, thB[3], z ? NEGB : bqM[3], z ? NEGB : bqX[3], z ? NEGB : bqY[3]);
        shiftB();
    }

    // lane 31 of the last strip holds V(1536, 1536); terminal smoothed max.
    if (g == STRIPS - 1 && r == 31) {
        out[0] = LN2 * lse3_(vM, vX, vY);
    }
}

extern "C" void kernel_launch(void* const* d_in, const int* in_sizes, int n_in,
                              void* d_out, int out_size)
{
    const float* theta = (const float*)d_in[0];
    float* out = (float*)d_out;
    hmm_init_kernel<<<1, 64>>>();
    hmm_fwd_kernel<<<STRIPS, 32>>>(theta, out);
}

// round 6
// speedup vs baseline: 1.0876x; 1.0876x over previous
#include <cuda_runtime.h>
#include <cstddef>
#include <cstdint>

#define MM 1536
#define STRIPS 48
#define TSTEPS 1568   /* multiple of 8, >= MM + 31 */

#define L2E  1.4426950408889634f
#define LN2  0.6931471805599453f
#define NEGB (-1.0e8f * L2E)

// Pre-skewed, pre-scaled theta: th2[((g*TSTEPS + t)*9 + e)*32 + r]
//   = theta[row=32g+r][col=t-r][e] * L2E   (junk where col out of range; DP guards)
__device__ float g_th2[(size_t)STRIPS * TSTEPS * 9 * 32];

// Strip boundary rows + progress flags (release/acquire over L2)
__device__ float g_bM[STRIPS][MM + 32];
__device__ float g_bX[STRIPS][MM + 32];
__device__ float g_bY[STRIPS][MM + 32];
__device__ int   g_prog[STRIPS];

__global__ void hmm_init_kernel() {
    if (threadIdx.x < STRIPS) g_prog[threadIdx.x] = 0;
}

// ---------------- memory-order helpers (no CCTL.IVALL, L2-scope only) -------
__device__ __forceinline__ int ld_acq(const int* p) {
    int v; asm volatile("ld.acquire.gpu.global.s32 %0, [%1];" : "=r"(v) : "l"(p) : "memory"); return v;
}
__device__ __forceinline__ void st_rel(int* p, int v) {
    asm volatile("st.release.gpu.global.s32 [%0], %1;" :: "l"(p), "r"(v) : "memory");
}
__device__ __forceinline__ float ld_rlx(const float* p) {
    float v; asm volatile("ld.relaxed.gpu.global.f32 %0, [%1];" : "=f"(v) : "l"(p) : "memory"); return v;
}
__device__ __forceinline__ void st_rlx(float* p, float v) {
    asm volatile("st.relaxed.gpu.global.f32 [%0], %1;" :: "l"(p), "f"(v) : "memory");
}

__device__ __forceinline__ float ex2_(float x) {
    float y; asm("ex2.approx.ftz.f32 %0, %1;" : "=f"(y) : "f"(x)); return y;
}
__device__ __forceinline__ float lg2_(float x) {
    float y; asm("lg2.approx.ftz.f32 %0, %1;" : "=f"(y) : "f"(x)); return y;
}
// logsumexp of 3 in base-2 domain; max term contributes exactly 1.
__device__ __forceinline__ float lse3_(float a, float b, float c) {
    float hi = fmaxf(a, b), lo = fminf(a, b);
    float m  = fmaxf(hi, c), s2 = fminf(hi, c);
    return m + lg2_(1.0f + ex2_(lo - m) + ex2_(s2 - m));
}

// ---------------- transpose: theta -> skewed coalesced layout ----------------
#define TT 32
#define RG 8
#define NCOL (TT + RG - 1)     /* 39 */
#define SROW (NCOL * 9)        /* 351 */

__global__ void __launch_bounds__(256)
hmm_transpose_kernel(const float* __restrict__ theta)
{
    __shared__ float s[RG][SROW];
    const int g    = blockIdx.x;          // strip
    const int T0   = blockIdx.y * TT;     // t tile
    const int r0   = blockIdx.z * RG;     // lane group
    const int tid  = threadIdx.x;
    const long NTOT = (long)MM * MM * 9;
    const int C0   = T0 - r0 - (RG - 1);

    #pragma unroll
    for (int row = 0; row < RG; row++) {
        long base = (long)(32 * g + r0 + row) * (MM * 9) + (long)C0 * 9;
        for (int i = tid; i < SROW; i += 256) {
            long idx = base + i;
            idx = idx < 0 ? 0 : (idx >= NTOT ? NTOT - 1 : idx);   // clamp: junk OK (guarded in DP)
            s[row][i] = theta[idx] * L2E;
        }
    }
    __syncthreads();

    float* outb = g_th2 + ((size_t)g * TSTEPS + T0) * 288 + r0;
    #pragma unroll
    for (int k = 0; k < 9; k++) {
        int flat = tid + k * 256;          // 0..2303
        int row  = flat & 7;
        int te   = flat >> 3;              // t_i*9 + e, 0..287
        int t_i  = te / 9;
        int e    = te - t_i * 9;
        float v  = s[row][(t_i - row + 7) * 9 + e];
        outb[(size_t)t_i * 288 + e * 32 + row] = v;
    }
}

// ---------------- wavefront DP kernel ---------------------------------------
__global__ void __launch_bounds__(32, 1)
hmm_fwd_kernel(float* __restrict__ out)
{
    const int g = blockIdx.x;    // strip: DP rows 32g+1 .. 32g+32
    const int r = threadIdx.x;   // lane -> DP row 32g + r + 1
    const float* tb2 = g_th2 + (size_t)g * TSTEPS * 288 + r;

    float vM = NEGB, vX = NEGB, vY = NEGB;
    float duM, duX, duY;
    duM = duX = duY = (g == 0 && r == 0) ? 0.0f : NEGB;  // V(0,0)=0

    // boundary ring (lane 0 of g>0): bq[i] = col t0+1+i for current 8-step chunk
    float bqM[8], bqX[8], bqY[8], tmpM[8], tmpX[8], tmpY[8];
    #pragma unroll
    for (int q = 0; q < 8; q++) {
        bqM[q] = NEGB; bqX[q] = NEGB; bqY[q] = NEGB;
        tmpM[q] = NEGB; tmpX[q] = NEGB; tmpY[q] = NEGB;
    }
    int avail = 0, availNext = 0;

    float thA[4][9], thB[4][9];
    auto loadGroup = [&](int tbase, float (&dst)[4][9]) {
        #pragma unroll
        for (int q = 0; q < 4; q++) {
            int t = tbase + q; if (t > TSTEPS - 1) t = TSTEPS - 1;
            const float* p = tb2 + (size_t)t * 288;
            #pragma unroll
            for (int e = 0; e < 9; e++) dst[q][e] = __ldg(p + e * 32);   // coalesced
        }
    };

    auto step = [&](int t, const float (&th)[9], float bM_, float bX_, float bY_) {
        float nuM = __shfl_up_sync(0xffffffffu, vM, 1);
        float nuX = __shfl_up_sync(0xffffffffu, vX, 1);
        float nuY = __shfl_up_sync(0xffffffffu, vY, 1);
        if (r == 0) { nuM = bM_; nuX = bX_; nuY = bY_; }
        int col = t - r;
        if ((unsigned)col < (unsigned)MM) {
            float a = lse3_(duM + th[0], duX + th[1], duY + th[2]);  // Match <- diag
            float b = lse3_(nuM + th[3], nuX + th[4], nuY + th[5]);  // X     <- up
            float c = lse3_(vM  + th[6], vX  + th[7], vY  + th[8]);  // Y     <- left
            vM = a; vX = b; vY = c;
            if (r == 31 && g < STRIPS - 1) {
                int j = col + 1;
                st_rlx(&g_bM[g][j], a);
                st_rlx(&g_bX[g][j], b);
                st_rlx(&g_bY[g][j], c);
                if ((j & 7) == 0 || j == MM) st_rel(&g_prog[g], j);
            }
        }
        duM = nuM; duX = nuX; duY = nuY;
    };

    // ---- prologue ----
    loadGroup(0, thA);
    loadGroup(4, thB);
    if (g > 0 && r == 0) {
        const int* fp = &g_prog[g - 1];
        do { avail = ld_acq(fp); } while (avail < 16);
        #pragma unroll
        for (int q = 0; q < 8; q++) {
            bqM[q] = ld_rlx(&g_bM[g - 1][1 + q]);
            bqX[q] = ld_rlx(&g_bX[g - 1][1 + q]);
            bqY[q] = ld_rlx(&g_bY[g - 1][1 + q]);
            tmpM[q] = ld_rlx(&g_bM[g - 1][9 + q]);
            tmpX[q] = ld_rlx(&g_bX[g - 1][9 + q]);
            tmpY[q] = ld_rlx(&g_bY[g - 1][9 + q]);
        }
        availNext = ld_acq(fp);
    }

    const bool z = (g == 0);  // top strip: row above = V[0,:] border (NEGB for col>=1)

    // ---- main loop: 8-step chunks ----
    for (int t0 = 0; t0 < TSTEPS; t0 += 8) {
        step(t0 + 0, thA[0], z ? NEGB : bqM[0], z ? NEGB : bqX[0], z ? NEGB : bqY[0]);
        step(t0 + 1, thA[1], z ? NEGB : bqM[1], z ? NEGB : bqX[1], z ? NEGB : bqY[1]);
        step(t0 + 2, thA[2], z ? NEGB : bqM[2], z ? NEGB : bqX[2], z ? NEGB : bqY[2]);
        step(t0 + 3, thA[3], z ? NEGB : bqM[3], z ? NEGB : bqX[3], z ? NEGB : bqY[3]);
        loadGroup(t0 + 8, thA);
        step(t0 + 4, thB[0], z ? NEGB : bqM[4], z ? NEGB : bqX[4], z ? NEGB : bqY[4]);
        step(t0 + 5, thB[1], z ? NEGB : bqM[5], z ? NEGB : bqX[5], z ? NEGB : bqY[5]);
        step(t0 + 6, thB[2], z ? NEGB : bqM[6], z ? NEGB : bqX[6], z ? NEGB : bqY[6]);
        step(t0 + 7, thB[3], z ? NEGB : bqM[7], z ? NEGB : bqX[7], z ? NEGB : bqY[7]);
        loadGroup(t0 + 12, thB);

        // chunk-end boundary maintenance (lane 0 of non-top strips)
        if (g > 0 && r == 0) {
            #pragma unroll
            for (int q = 0; q < 8; q++) { bqM[q] = tmpM[q]; bqX[q] = tmpX[q]; bqY[q] = tmpY[q]; }
            avail = avail > availNext ? avail : availNext;
            int need = t0 + 24; if (need > MM) need = MM;
            const int* fp = &g_prog[g - 1];
            while (avail < need) avail = ld_acq(fp);
            #pragma unroll
            for (int q = 0; q < 8; q++) {
                int c = t0 + 17 + q; if (c > MM) c = MM;
                tmpM[q] = ld_rlx(&g_bM[g - 1][c]);
                tmpX[q] = ld_rlx(&g_bX[g - 1][c]);
                tmpY[q] = ld_rlx(&g_bY[g - 1][c]);
            }
            availNext = ld_acq(fp);   // prefetch flag for next chunk (hides L2 latency)
        }
    }

    if (g == STRIPS - 1 && r == 31) {
        out[0] = LN2 * lse3_(vM, vX, vY);
    }
}

extern "C" void kernel_launch(void* const* d_in, const int* in_sizes, int n_in,
                              void* d_out, int out_size)
{
    const float* theta = (const float*)d_in[0];
    float* out = (float*)d_out;
    dim3 tgrid(STRIPS, TSTEPS / TT, 32 / RG);
    hmm_transpose_kernel<<<tgrid, 256>>>(theta);
    hmm_init_kernel<<<1, 64>>>();
    hmm_fwd_kernel<<<STRIPS, 32>>>(out);
}